// round 6
// baseline (speedup 1.0000x reference)
#include <cuda_runtime.h>
#include <cuda_fp16.h>
#include <cstdint>

// DigitCapsules dynamic routing, GB300 sm_103a
// B=256, C=10, I=1152, DI=8, DO=16, 3 routing iterations.
//
// Route kernel is fma-pipe ISSUE-THROUGHPUT bound on the busiest SMSP
// (10 warps/block -> 3/3/2/2 placement, 2 CTAs/SM -> 6-warp SMSP).
// Fix: packed f32x2 FFMA2 (exact fp32, one slot per 2 FMAs) for dot and
// accumulation; uhat uses a [c][k][d]-transposed W smem tile so one FFMA2
// produces two d-outputs.

#define BSZ  256
#define CCL  10
#define ICAP 1152
#define DOV  16
#define DIV  8
#define NGRP 18          // groups of 2 tiles (32 i each) -> 18*64 = 1152

typedef unsigned long long ull;

__device__ __align__(256) __half g_uhat[(size_t)BSZ * CCL * ICAP * DOV]; // 94.4 MB

// ---------------- packed f32x2 helpers (exact fp32 SIMD-2) ------------------
static __device__ __forceinline__ ull pack2(float x, float y) {
    ull r; asm("mov.b64 %0, {%1, %2};" : "=l"(r) : "f"(x), "f"(y)); return r;
}
static __device__ __forceinline__ void unpack2(ull v, float& x, float& y) {
    asm("mov.b64 {%0, %1}, %2;" : "=f"(x), "=f"(y) : "l"(v));
}
static __device__ __forceinline__ ull fma2(ull a, ull b, ull c) {
    ull d; asm("fma.rn.f32x2 %0, %1, %2, %3;" : "=l"(d) : "l"(a), "l"(b), "l"(c));
    return d;
}
static __device__ __forceinline__ ull mul2(ull a, ull b) {
    ull d; asm("mul.rn.f32x2 %0, %1, %2;" : "=l"(d) : "l"(a), "l"(b)); return d;
}
static __device__ __forceinline__ ull add2(ull a, ull b) {
    ull d; asm("add.rn.f32x2 %0, %1, %2;" : "=l"(d) : "l"(a), "l"(b)); return d;
}
static __device__ __forceinline__ ull h2f2(__half2 h) {
    float2 f = __half22float2(h);
    return pack2(f.x, f.y);
}
static __device__ __forceinline__ unsigned int pack_h2(float a, float b) {
    __half2 h = __floats2half2_rn(a, b);
    return *reinterpret_cast<unsigned int*>(&h);
}

// ---------------------------------------------------------------------------
// K_uhat: u_hat[b,c,i,do] = sum_k W[c,i,0,do,k] * x[b,i,k]   (fp32 -> fp16)
// grid = I (block per input capsule), 256 threads = b.
// W staged transposed [c][k][d] so LDS.64 pairs (d, d+1) feed FFMA2 directly:
// one packed chain yields two d-outputs.
// ---------------------------------------------------------------------------
__global__ __launch_bounds__(256) void uhat_kernel(
    const float* __restrict__ x, const float* __restrict__ W)
{
    const int i = blockIdx.x;
    const int b = threadIdx.x;

    __shared__ float Ws[CCL][DIV][DOV];   // [c][k][d] : 5120 B

    for (int f = threadIdx.x; f < CCL * DOV * DIV; f += 256) {
        int c   = f / (DOV * DIV);
        int rem = f - c * (DOV * DIV);
        int d   = rem >> 3;       // DIV = 8
        int k   = rem & 7;
        Ws[c][k][d] = W[(((size_t)c * ICAP + i) * DOV + d) * DIV + k];
    }

    // x row packed as {x_k, x_k} broadcast pairs
    const float* xp = x + (size_t)b * (ICAP * DIV) + (size_t)i * DIV;
    const float4 x0 = *reinterpret_cast<const float4*>(xp);
    const float4 x1 = *reinterpret_cast<const float4*>(xp + 4);
    ull xx[8];
    xx[0] = pack2(x0.x, x0.x); xx[1] = pack2(x0.y, x0.y);
    xx[2] = pack2(x0.z, x0.z); xx[3] = pack2(x0.w, x0.w);
    xx[4] = pack2(x1.x, x1.x); xx[5] = pack2(x1.y, x1.y);
    xx[6] = pack2(x1.z, x1.z); xx[7] = pack2(x1.w, x1.w);

    __syncthreads();

    __half* up = g_uhat + (size_t)b * (CCL * ICAP * DOV) + (size_t)i * DOV;

    #pragma unroll
    for (int c = 0; c < CCL; c++) {
        unsigned int h[8];
        #pragma unroll
        for (int dp = 0; dp < 8; dp++) {
            // Ws[c][k][2dp..2dp+1] for k=0..7; row stride = DOV floats = 8 ull
            const ull* wp = reinterpret_cast<const ull*>(&Ws[c][0][dp * 2]);
            ull a0 = mul2(wp[0],  xx[0]);
            ull a1 = mul2(wp[8],  xx[1]);
            a0 = fma2(wp[16], xx[2], a0);
            a1 = fma2(wp[24], xx[3], a1);
            a0 = fma2(wp[32], xx[4], a0);
            a1 = fma2(wp[40], xx[5], a1);
            a0 = fma2(wp[48], xx[6], a0);
            a1 = fma2(wp[56], xx[7], a1);
            a0 = add2(a0, a1);
            float r0, r1; unpack2(a0, r0, r1);
            h[dp] = pack_h2(r0, r1);      // u_hat[b,c,i,2dp..2dp+1]
        }
        __half* o = up + (size_t)c * (ICAP * DOV);
        *reinterpret_cast<uint4*>(o)     = make_uint4(h[0], h[1], h[2], h[3]);
        *reinterpret_cast<uint4*>(o + 8) = make_uint4(h[4], h[5], h[6], h[7]);
    }
}

// unpack one packed tile row (2x uint4 of half2) into 8 packed f32x2
static __device__ __forceinline__ void unpack_tile(const uint4& a, const uint4& b,
                                                   ull* __restrict__ u) {
    const __half2* ha = reinterpret_cast<const __half2*>(&a);
    const __half2* hb = reinterpret_cast<const __half2*>(&b);
    #pragma unroll
    for (int q = 0; q < 4; q++) u[q]     = h2f2(ha[q]);
    #pragma unroll
    for (int q = 0; q < 4; q++) u[4 + q] = h2f2(hb[q]);
}

// packed dot: sum over 16 dims of u . vr
static __device__ __forceinline__ float dotp(const ull* __restrict__ u,
                                             const ull* __restrict__ vrp) {
    ull d0 = mul2(u[0], vrp[0]);
    ull d1 = mul2(u[1], vrp[1]);
    d0 = fma2(u[2], vrp[2], d0);
    d1 = fma2(u[3], vrp[3], d1);
    d0 = fma2(u[4], vrp[4], d0);
    d1 = fma2(u[5], vrp[5], d1);
    d0 = fma2(u[6], vrp[6], d0);
    d1 = fma2(u[7], vrp[7], d1);
    d0 = add2(d0, d1);
    float lo, hi; unpack2(d0, lo, hi);
    return lo + hi;
}

// ---------------------------------------------------------------------------
// route_kernel: all 3 routing iterations for one batch element.
// grid = B, 320 threads: warp = class c, lane ii = i-slot (32 i per tile).
// Tiles in groups of 2, one barrier per group, double-buffered e_s.
// ---------------------------------------------------------------------------
__global__ __launch_bounds__(320, 2) void route_kernel(float* __restrict__ out)
{
    const int b  = blockIdx.x;
    const int c  = threadIdx.x >> 5;
    const int ii = threadIdx.x & 31;

    __shared__ float e_s[2][2][CCL][33];   // [parity][tile-in-group][c][i]

    const __half* ub = g_uhat + ((size_t)b * CCL + c) * (size_t)ICAP * DOV;

    ull vrp[8];    // packed running vacc
    ull sacp[8];   // packed s accumulators
    float vr[DOV];

    // ---------------- iteration 0: uniform weights 0.1, no barriers
    {
        const ull w2 = pack2(0.1f, 0.1f);
        #pragma unroll
        for (int j = 0; j < 8; j++) sacp[j] = pack2(0.0f, 0.0f);

        for (int g = 0; g < NGRP; g++) {
            const __half* tb = ub + (size_t)(g * 64 + ii) * DOV;
            const uint4* q0 = reinterpret_cast<const uint4*>(tb);
            const uint4* q1 = reinterpret_cast<const uint4*>(tb + 32 * DOV);
            uint4 A0 = q0[0], B0 = q0[1];
            uint4 A1 = q1[0], B1 = q1[1];

            ull u[8];
            unpack_tile(A0, B0, u);
            #pragma unroll
            for (int j = 0; j < 8; j++) sacp[j] = fma2(w2, u[j], sacp[j]);
            unpack_tile(A1, B1, u);
            #pragma unroll
            for (int j = 0; j < 8; j++) sacp[j] = fma2(w2, u[j], sacp[j]);
        }
    }
    // reduce + squash -> vr, vrp
    {
        float sac[DOV];
        #pragma unroll
        for (int j = 0; j < 8; j++) unpack2(sacp[j], sac[2 * j], sac[2 * j + 1]);
        #pragma unroll
        for (int off = 16; off > 0; off >>= 1)
            #pragma unroll
            for (int j = 0; j < DOV; j++)
                sac[j] += __shfl_xor_sync(0xffffffffu, sac[j], off);
        float sq = 0.0f;
        #pragma unroll
        for (int j = 0; j < DOV; j++) sq = fmaf(sac[j], sac[j], sq);
        float scale = __fdividef(sqrtf(sq), 1.0f + sq);
        #pragma unroll
        for (int j = 0; j < DOV; j++) vr[j] = sac[j] * scale;
        #pragma unroll
        for (int j = 0; j < 8; j++) vrp[j] = pack2(vr[2 * j], vr[2 * j + 1]);
    }

    // ---------------- iterations 1 and 2
    #pragma unroll 1
    for (int t = 1; t < 3; t++) {
        #pragma unroll
        for (int j = 0; j < 8; j++) sacp[j] = pack2(0.0f, 0.0f);

        for (int g = 0; g < NGRP; g++) {
            const __half* tb = ub + (size_t)(g * 64 + ii) * DOV;
            const uint4* q0 = reinterpret_cast<const uint4*>(tb);
            const uint4* q1 = reinterpret_cast<const uint4*>(tb + 32 * DOV);
            uint4 A0 = q0[0], B0 = q0[1];
            uint4 A1 = q1[0], B1 = q1[1];

            ull u0[8], u1[8];
            unpack_tile(A0, B0, u0);
            unpack_tile(A1, B1, u1);

            const int p = g & 1;
            // |logit| bounded (~35): exp safe in fp32 without max-subtract
            e_s[p][0][c][ii] = __expf(dotp(u0, vrp));
            e_s[p][1][c][ii] = __expf(dotp(u1, vrp));
            __syncthreads();

            #pragma unroll
            for (int k = 0; k < 2; k++) {
                float Z = e_s[p][k][0][ii];
                #pragma unroll
                for (int cc = 1; cc < CCL; cc++) Z += e_s[p][k][cc][ii];
                float w = __fdividef(e_s[p][k][c][ii], Z);
                ull w2 = pack2(w, w);
                const ull* uu = k ? u1 : u0;
                #pragma unroll
                for (int j = 0; j < 8; j++) sacp[j] = fma2(w2, uu[j], sacp[j]);
            }
        }

        float sac[DOV];
        #pragma unroll
        for (int j = 0; j < 8; j++) unpack2(sacp[j], sac[2 * j], sac[2 * j + 1]);
        #pragma unroll
        for (int off = 16; off > 0; off >>= 1)
            #pragma unroll
            for (int j = 0; j < DOV; j++)
                sac[j] += __shfl_xor_sync(0xffffffffu, sac[j], off);

        float sq = 0.0f;
        #pragma unroll
        for (int j = 0; j < DOV; j++) sq = fmaf(sac[j], sac[j], sq);
        float scale = __fdividef(sqrtf(sq), 1.0f + sq);

        if (t == 2) {
            if (ii == 0) {
                float4* op = reinterpret_cast<float4*>(
                    out + ((size_t)b * CCL + c) * DOV);
                op[0] = make_float4(sac[0]*scale,  sac[1]*scale,  sac[2]*scale,  sac[3]*scale);
                op[1] = make_float4(sac[4]*scale,  sac[5]*scale,  sac[6]*scale,  sac[7]*scale);
                op[2] = make_float4(sac[8]*scale,  sac[9]*scale,  sac[10]*scale, sac[11]*scale);
                op[3] = make_float4(sac[12]*scale, sac[13]*scale, sac[14]*scale, sac[15]*scale);
            }
        } else {
            #pragma unroll
            for (int j = 0; j < DOV; j++) vr[j] = fmaf(sac[j], scale, vr[j]);
            #pragma unroll
            for (int j = 0; j < 8; j++) vrp[j] = pack2(vr[2 * j], vr[2 * j + 1]);
        }
    }
}

// ---------------------------------------------------------------------------
extern "C" void kernel_launch(void* const* d_in, const int* in_sizes, int n_in,
                              void* d_out, int out_size)
{
    const float* x = (const float*)d_in[0];
    const float* W = (const float*)d_in[1];
    if (in_sizes[0] == CCL * ICAP * DOV * DIV) {  // defensively identify by size
        const float* t = x; x = W; W = t;
    }
    float* out = (float*)d_out;

    uhat_kernel<<<ICAP, 256>>>(x, W);
    route_kernel<<<BSZ, 320>>>(out);
}